// round 14
// baseline (speedup 1.0000x reference)
#include <cuda_runtime.h>
#include <cuda_fp16.h>

#define B_   4
#define S_   2048
#define D_   1024
#define M_   (B_ * S_)          // 8192
#define NCH  64
#define CH   (S_ / NCH)         // 32

// ---------------- scratch ----------------------------------------------------
__device__ __align__(256) __half g_q  [(size_t)M_ * D_];
__device__ __align__(256) __half g_avg[(size_t)M_ * D_];
__device__ __align__(256) __half g_h  [(size_t)M_ * D_];
__device__ __align__(256) __half g_f  [(size_t)M_ * D_];
__device__ __align__(256) __half g_W1t[(size_t)D_ * D_];        // [N, K]
__device__ __align__(256) __half g_W2t[(size_t)D_ * D_];
__device__ __align__(256) __half g_Wgt[(size_t)2 * D_ * 2 * D_];
__device__ __align__(256) float g_acc [(size_t)M_ * 2 * D_];    // gate partial acc
__device__ float g_part[B_ * NCH * D_];

// ---------------- helpers ----------------------------------------------------
__device__ __forceinline__ unsigned smem_u32(const void* p) {
    unsigned r;
    asm("{ .reg .u64 t; cvta.to.shared.u64 t, %1; cvt.u32.u64 %0, t; }" : "=r"(r) : "l"(p));
    return r;
}
__device__ __forceinline__ unsigned pk_f16(float a, float b) {
    return (unsigned)__half_as_ushort(__float2half_rn(a)) |
           ((unsigned)__half_as_ushort(__float2half_rn(b)) << 16);
}
__device__ __forceinline__ void ldsm4(unsigned& r0, unsigned& r1, unsigned& r2, unsigned& r3,
                                      unsigned addr) {
    asm volatile("ldmatrix.sync.aligned.m8n8.x4.shared.b16 {%0,%1,%2,%3}, [%4];"
                 : "=r"(r0), "=r"(r1), "=r"(r2), "=r"(r3) : "r"(addr));
}
__device__ __forceinline__ void mma_f16(float* c, unsigned a0, unsigned a1, unsigned a2,
                                        unsigned a3, unsigned b0, unsigned b1) {
    asm volatile(
        "mma.sync.aligned.m16n8k16.row.col.f32.f16.f16.f32 "
        "{%0,%1,%2,%3}, {%4,%5,%6,%7}, {%8,%9}, {%0,%1,%2,%3};"
        : "+f"(c[0]), "+f"(c[1]), "+f"(c[2]), "+f"(c[3])
        : "r"(a0), "r"(a1), "r"(a2), "r"(a3), "r"(b0), "r"(b1));
}

// ---------------- scan: causal cumulative mean -------------------------------
__global__ void k_partial_sums(const float* __restrict__ iV) {
    int b = blockIdx.x, ch = blockIdx.y, d = threadIdx.x;
    const float* p = iV + ((size_t)b * S_ + (size_t)ch * CH) * D_ + d;
    float s = 0.f;
#pragma unroll 8
    for (int t = 0; t < CH; t++) s += p[(size_t)t * D_];
    g_part[(b * NCH + ch) * D_ + d] = s;
}

__global__ void k_exclusive_prefix() {
    int b = blockIdx.x, d = threadIdx.x;
    float run = 0.f;
#pragma unroll
    for (int ch = 0; ch < NCH; ch++) {
        int idx = (b * NCH + ch) * D_ + d;
        float v = g_part[idx];
        g_part[idx] = run;
        run += v;
    }
}

__global__ void k_cumavg(const float* __restrict__ iV) {
    int b = blockIdx.x, ch = blockIdx.y, d = threadIdx.x;
    float run = g_part[(b * NCH + ch) * D_ + d];
    const float* p = iV + ((size_t)b * S_ + (size_t)ch * CH) * D_ + d;
    size_t mrow = (size_t)b * S_ + (size_t)ch * CH;
#pragma unroll 4
    for (int t = 0; t < CH; t++) {
        run += p[(size_t)t * D_];
        int s = ch * CH + t;
        float x = run * (1.0f / (float)(s + 1));
        g_avg[(mrow + t) * D_ + d] = __float2half_rn(x);
    }
}

// ---------------- conversions ------------------------------------------------
__global__ __launch_bounds__(256) void k_convert_iQ(const float* __restrict__ iQ) {
    size_t t = (size_t)blockIdx.x * blockDim.x + threadIdx.x;   // M_*D_/32 threads
    size_t m  = t / (D_ / 32);
    int    dq = (int)(t % (D_ / 32)) * 32;
    const float4* src = (const float4*)(iQ + m * D_ + dq);
    unsigned w[16];
#pragma unroll
    for (int i = 0; i < 8; i++) {
        float4 x = src[i];
        w[2 * i]     = pk_f16(x.x, x.y);
        w[2 * i + 1] = pk_f16(x.z, x.w);
    }
    uint4* dst = (uint4*)(g_q + m * D_ + dq);
#pragma unroll
    for (int i = 0; i < 4; i++)
        dst[i] = make_uint4(w[4 * i], w[4 * i + 1], w[4 * i + 2], w[4 * i + 3]);
}

// W [K,N] fp32 -> Wt [N, K] fp16, via smem transpose
__global__ __launch_bounds__(256) void k_convert_W(const float* __restrict__ W,
                                                   __half* __restrict__ Wt,
                                                   int K, int N) {
    __shared__ float t[64][65];
    const int tid = threadIdx.x;
    const int n0 = blockIdx.x * 64, k0 = blockIdx.y * 64;
    {
        const int r = tid >> 4;
        const int c4 = tid & 15;
#pragma unroll
        for (int i = 0; i < 4; i++) {
            int k = r + 16 * i;
            float4 v = *(const float4*)(W + (size_t)(k0 + k) * N + n0 + 4 * c4);
            t[k][4 * c4 + 0] = v.x;
            t[k][4 * c4 + 1] = v.y;
            t[k][4 * c4 + 2] = v.z;
            t[k][4 * c4 + 3] = v.w;
        }
    }
    __syncthreads();
    const int n = tid >> 2;
    const int kq = tid & 3;              // 16 orig-k each
    unsigned w[8];
#pragma unroll
    for (int j = 0; j < 8; j++)
        w[j] = pk_f16(t[16 * kq + 2 * j][n], t[16 * kq + 2 * j + 1][n]);
    uint4* dst = (uint4*)(Wt + (size_t)(n0 + n) * K + k0 + 16 * kq);
    dst[0] = make_uint4(w[0], w[1], w[2], w[3]);
    dst[1] = make_uint4(w[4], w[5], w[6], w[7]);
}

// ================= GEMM A: 128x128 tile, 256 threads, occ 2 ===================
#define BK 64
#define STAGES 3
#define STG_A (2 * 128 * 128)                // 32 KB per stage
#define SMEM_A (STAGES * STG_A)              // 96 KB

template <int SEL>
__global__ __launch_bounds__(256, 2)
void k_gemm_small(const __half* __restrict__ A0,
                  const __half* __restrict__ Bw,
                  const float* __restrict__ bias)
{
    extern __shared__ __align__(1024) char dsmem[];
    const unsigned sbase = smem_u32(dsmem);

    const int tid = threadIdx.x;
    const int warp = tid >> 5, lid = tid & 31;
    const int wm = warp >> 2;            // 0..1 -> 64 rows
    const int wn = warp & 3;             // 0..3 -> 32 cols
    const int m0 = blockIdx.y * 128;
    const int n0 = blockIdx.x * 128;
    const int NB = D_ / BK;              // 16

    const int lrow = tid >> 1;           // 0..127
    const int lcb  = (tid & 1) * 4;
    const int lswz = lrow & 7;

    float acc[4][4][4];
#pragma unroll
    for (int i = 0; i < 4; i++)
#pragma unroll
        for (int j = 0; j < 4; j++)
#pragma unroll
            for (int k = 0; k < 4; k++) acc[i][j][k] = 0.f;

    auto load_blk = [&](int kb, int stage) {
        unsigned sA = sbase + stage * STG_A;
        unsigned sB = sA + 128 * 128;
        unsigned long long ag =
            (unsigned long long)(A0 + (size_t)(m0 + lrow) * D_ + (size_t)kb * BK);
        unsigned asm_ = sA + lrow * 128;
#pragma unroll
        for (int i = 0; i < 4; i++) {
            int c = lcb + i;
            asm volatile("cp.async.cg.shared.global [%0], [%1], 16;"
                         :: "r"(asm_ + (unsigned)((c ^ lswz) << 4)), "l"(ag + c * 16) : "memory");
        }
        unsigned long long bg2 =
            (unsigned long long)(Bw + (size_t)(n0 + lrow) * D_ + (size_t)kb * BK);
        unsigned bsm = sB + lrow * 128;
#pragma unroll
        for (int i = 0; i < 4; i++) {
            int c = lcb + i;
            asm volatile("cp.async.cg.shared.global [%0], [%1], 16;"
                         :: "r"(bsm + (unsigned)((c ^ lswz) << 4)), "l"(bg2 + c * 16) : "memory");
        }
        asm volatile("cp.async.commit_group;" ::: "memory");
    };

    int arow[4], brow[2];
#pragma unroll
    for (int mt = 0; mt < 4; mt++)
        arow[mt] = wm * 64 + mt * 16 + (lid & 7) + ((lid >> 3) & 1) * 8;
    const int ahi = lid >> 4;
#pragma unroll
    for (int p = 0; p < 2; p++)
        brow[p] = wn * 32 + p * 16 + (lid & 7) + (lid >> 4) * 8;
    const int bhi = (lid >> 3) & 1;

#pragma unroll
    for (int s = 0; s < STAGES - 1; s++) load_blk(s, s);

    for (int kb = 0; kb < NB; kb++) {
        asm volatile("cp.async.wait_group %0;" :: "n"(STAGES - 2) : "memory");
        __syncthreads();
        if (kb + STAGES - 1 < NB) load_blk(kb + STAGES - 1, (kb + STAGES - 1) % STAGES);

        unsigned sA = sbase + (kb % STAGES) * STG_A;
        unsigned sB = sA + 128 * 128;
#pragma unroll
        for (int ks = 0; ks < 4; ks++) {
            unsigned a[4][4], b[2][4];
#pragma unroll
            for (int mt = 0; mt < 4; mt++)
                ldsm4(a[mt][0], a[mt][1], a[mt][2], a[mt][3],
                      sA + arow[mt] * 128 + (unsigned)(((2 * ks + ahi) ^ (arow[mt] & 7)) << 4));
#pragma unroll
            for (int p = 0; p < 2; p++)
                ldsm4(b[p][0], b[p][1], b[p][2], b[p][3],
                      sB + brow[p] * 128 + (unsigned)(((2 * ks + bhi) ^ (brow[p] & 7)) << 4));
#pragma unroll
            for (int mt = 0; mt < 4; mt++)
#pragma unroll
                for (int nt = 0; nt < 4; nt++)
                    mma_f16(acc[mt][nt], a[mt][0], a[mt][1], a[mt][2], a[mt][3],
                            b[nt >> 1][(nt & 1) * 2], b[nt >> 1][(nt & 1) * 2 + 1]);
        }
    }

    const int gid = lid >> 2, tig = lid & 3;
#pragma unroll
    for (int mt = 0; mt < 4; mt++) {
#pragma unroll
        for (int r2 = 0; r2 < 2; r2++) {
            const int m = m0 + wm * 64 + mt * 16 + gid + r2 * 8;
#pragma unroll
            for (int nt = 0; nt < 4; nt++) {
                const int n = n0 + wn * 32 + nt * 8 + 2 * tig;
                float2 bb = *(const float2*)(bias + n);
                float v0 = acc[mt][nt][r2 * 2 + 0] + bb.x;
                float v1 = acc[mt][nt][r2 * 2 + 1] + bb.y;
                if (SEL == 0) {
                    v0 = fmaxf(v0, 0.f); v1 = fmaxf(v1, 0.f);
                    *(unsigned*)(g_h + (size_t)m * D_ + n) = pk_f16(v0, v1);
                } else {
                    *(unsigned*)(g_f + (size_t)m * D_ + n) = pk_f16(v0, v1);
                }
            }
        }
    }
}

// ================= GEMM B: gate GEMM, split into two K-phases ==================
// PHASE 0: acc = q @ Wg[0:1024]   (paired cols) -> g_acc fp32     (overlaps G1/G2)
// PHASE 1: acc = f @ Wg[1024:2048] + g_acc + bias -> sigmoid ->
//          smem exchange -> out = igate*q + fgate*f
#define BM 128
#define BN 256
#define A_BYTES (BM * 128)                  // 16 KB
#define B_BYTES (BN * 128)                  // 32 KB
#define STG_B (A_BYTES + B_BYTES)           // 48 KB
#define SMEM_B (STAGES * STG_B)             // 144 KB

template <int PHASE>
__global__ __launch_bounds__(512, 1)
void k_gemm_gate(const __half* __restrict__ A0,     // PHASE 0: g_q, PHASE 1: g_f
                 const __half* __restrict__ Qp,     // g_q (combine), PHASE 1 only
                 const __half* __restrict__ Bw,     // g_Wgt
                 const float* __restrict__ bias,
                 float* __restrict__ out)
{
    extern __shared__ __align__(1024) char dsmem[];
    const unsigned sbase = smem_u32(dsmem);
    const int K = 2 * D_;                // Wg row length
    const int NB = 16;                   // one K-half

    const int tid = threadIdx.x;
    const int warp = tid >> 5, lid = tid & 31;
    const int wm = warp >> 3;            // 0..1
    const int wn = warp & 7;             // 0..7
    const int m0 = blockIdx.y * BM;
    const int cg0 = blockIdx.x * 128;    // gate col-pair base

    const int ar  = tid >> 2;            // 0..127
    const int ac0 = (tid & 3) * 2;
    const int br  = tid >> 1;            // 0..255
    const int bc0 = (tid & 1) * 4;

    float acc[4][4][4];
#pragma unroll
    for (int i = 0; i < 4; i++)
#pragma unroll
        for (int j = 0; j < 4; j++)
#pragma unroll
            for (int k = 0; k < 4; k++) acc[i][j][k] = 0.f;

    auto load_blk = [&](int kb, int stage) {
        unsigned sA = sbase + stage * STG_B;
        unsigned sB = sA + A_BYTES;
        unsigned long long ag =
            (unsigned long long)(A0 + (size_t)(m0 + ar) * D_ + (size_t)kb * BK);
        unsigned asm_ = sA + ar * 128;
        const int aswz = ar & 7;
#pragma unroll
        for (int i = 0; i < 2; i++) {
            int c = ac0 + i;
            asm volatile("cp.async.cg.shared.global [%0], [%1], 16;"
                         :: "r"(asm_ + (unsigned)((c ^ aswz) << 4)), "l"(ag + c * 16) : "memory");
        }
        int gn = (br < 128) ? (cg0 + br) : (1024 + cg0 + br - 128);
        unsigned long long bg2 =
            (unsigned long long)(Bw + (size_t)gn * K + (size_t)(kb + PHASE * 16) * BK);
        unsigned bsm = sB + br * 128;
        const int bswz = br & 7;
#pragma unroll
        for (int i = 0; i < 4; i++) {
            int c = bc0 + i;
            asm volatile("cp.async.cg.shared.global [%0], [%1], 16;"
                         :: "r"(bsm + (unsigned)((c ^ bswz) << 4)), "l"(bg2 + c * 16) : "memory");
        }
        asm volatile("cp.async.commit_group;" ::: "memory");
    };

    int arow[4], brow[2];
#pragma unroll
    for (int mt = 0; mt < 4; mt++)
        arow[mt] = wm * 64 + mt * 16 + (lid & 7) + ((lid >> 3) & 1) * 8;
    const int ahi = lid >> 4;
#pragma unroll
    for (int p = 0; p < 2; p++)
        brow[p] = wn * 32 + p * 16 + (lid & 7) + (lid >> 4) * 8;
    const int bhi = (lid >> 3) & 1;

#pragma unroll
    for (int s = 0; s < STAGES - 1; s++) load_blk(s, s);

    for (int kb = 0; kb < NB; kb++) {
        asm volatile("cp.async.wait_group %0;" :: "n"(STAGES - 2) : "memory");
        __syncthreads();
        if (kb + STAGES - 1 < NB) load_blk(kb + STAGES - 1, (kb + STAGES - 1) % STAGES);

        unsigned sA = sbase + (kb % STAGES) * STG_B;
        unsigned sB = sA + A_BYTES;
#pragma unroll
        for (int ks = 0; ks < 4; ks++) {
            unsigned a[4][4], b[2][4];
#pragma unroll
            for (int mt = 0; mt < 4; mt++)
                ldsm4(a[mt][0], a[mt][1], a[mt][2], a[mt][3],
                      sA + arow[mt] * 128 + (unsigned)(((2 * ks + ahi) ^ (arow[mt] & 7)) << 4));
#pragma unroll
            for (int p = 0; p < 2; p++)
                ldsm4(b[p][0], b[p][1], b[p][2], b[p][3],
                      sB + brow[p] * 128 + (unsigned)(((2 * ks + bhi) ^ (brow[p] & 7)) << 4));
#pragma unroll
            for (int mt = 0; mt < 4; mt++)
#pragma unroll
                for (int nt = 0; nt < 4; nt++)
                    mma_f16(acc[mt][nt], a[mt][0], a[mt][1], a[mt][2], a[mt][3],
                            b[nt >> 1][(nt & 1) * 2], b[nt >> 1][(nt & 1) * 2 + 1]);
        }
    }

    const int gid = lid >> 2, tig = lid & 3;

    if (PHASE == 0) {
        // store raw partial accumulators (fp32)
#pragma unroll
        for (int mt = 0; mt < 4; mt++) {
#pragma unroll
            for (int r2 = 0; r2 < 2; r2++) {
                const int m = m0 + wm * 64 + mt * 16 + gid + r2 * 8;
#pragma unroll
                for (int nt = 0; nt < 4; nt++) {
                    const int nl = wn * 32 + nt * 8 + 2 * tig;
                    const int gcol = (nl < 128) ? (cg0 + nl) : (1024 + cg0 + nl - 128);
                    *(float2*)(g_acc + (size_t)m * (2 * D_) + gcol) =
                        make_float2(acc[mt][nt][r2 * 2 + 0], acc[mt][nt][r2 * 2 + 1]);
                }
            }
        }
        return;
    }

    // PHASE 1: add partial + bias, sigmoid, exchange, combine
    __syncthreads();
    float* gsm = (float*)dsmem;        // [128][260]
#pragma unroll
    for (int mt = 0; mt < 4; mt++) {
#pragma unroll
        for (int r2 = 0; r2 < 2; r2++) {
            const int ml = wm * 64 + mt * 16 + gid + r2 * 8;
            const int m = m0 + ml;
#pragma unroll
            for (int nt = 0; nt < 4; nt++) {
                const int nl = wn * 32 + nt * 8 + 2 * tig;
                const int gcol = (nl < 128) ? (cg0 + nl) : (1024 + cg0 + nl - 128);
                float2 bb = *(const float2*)(bias + gcol);
                float2 pp = *(const float2*)(g_acc + (size_t)m * (2 * D_) + gcol);
                float v0 = acc[mt][nt][r2 * 2 + 0] + pp.x + bb.x;
                float v1 = acc[mt][nt][r2 * 2 + 1] + pp.y + bb.y;
                v0 = 1.0f / (1.0f + __expf(-v0));
                v1 = 1.0f / (1.0f + __expf(-v1));
                gsm[ml * 260 + nl]     = v0;
                gsm[ml * 260 + nl + 1] = v1;
            }
        }
    }
    __syncthreads();
    const int c4 = tid & 31;
    const int r0 = tid >> 5;
#pragma unroll
    for (int i = 0; i < 8; i++) {
        const int r = r0 + 16 * i;
        const int col = 4 * c4;
        const size_t gidx = (size_t)(m0 + r) * D_ + cg0 + col;
        uint2 qw = *(const uint2*)(Qp + gidx);
        uint2 fw = *(const uint2*)(A0 + gidx);
        float2 q01 = __half22float2(*(__half2*)&qw.x);
        float2 q23 = __half22float2(*(__half2*)&qw.y);
        float2 f01 = __half22float2(*(__half2*)&fw.x);
        float2 f23 = __half22float2(*(__half2*)&fw.y);
        float4 gi = *(const float4*)&gsm[r * 260 + col];
        float4 gf = *(const float4*)&gsm[r * 260 + 128 + col];
        float4 o;
        o.x = gi.x * q01.x + gf.x * f01.x;
        o.y = gi.y * q01.y + gf.y * f01.y;
        o.z = gi.z * q23.x + gf.z * f23.x;
        o.w = gi.w * q23.y + gf.w * f23.y;
        *(float4*)(out + gidx) = o;
    }
}

// ---------------- launch ------------------------------------------------------
extern "C" void kernel_launch(void* const* d_in, const int* in_sizes, int n_in,
                              void* d_out, int out_size) {
    const float* iQ = (const float*)d_in[0];
    const float* iV = (const float*)d_in[1];
    const float* W1 = (const float*)d_in[2];
    const float* b1 = (const float*)d_in[3];
    const float* W2 = (const float*)d_in[4];
    const float* b2 = (const float*)d_in[5];
    const float* Wg = (const float*)d_in[6];
    const float* bg = (const float*)d_in[7];
    float* out = (float*)d_out;

    // one-time resources (host-side only; no device memory)
    static cudaStream_t s1 = nullptr, s2 = nullptr;
    static cudaEvent_t evRoot, evScan, evW2, evGp;
    if (s1 == nullptr) {
        cudaStreamCreateWithFlags(&s1, cudaStreamNonBlocking);
        cudaStreamCreateWithFlags(&s2, cudaStreamNonBlocking);
        cudaEventCreateWithFlags(&evRoot, cudaEventDisableTiming);
        cudaEventCreateWithFlags(&evScan, cudaEventDisableTiming);
        cudaEventCreateWithFlags(&evW2,   cudaEventDisableTiming);
        cudaEventCreateWithFlags(&evGp,   cudaEventDisableTiming);
        cudaFuncSetAttribute(k_gemm_small<0>, cudaFuncAttributeMaxDynamicSharedMemorySize, SMEM_A);
        cudaFuncSetAttribute(k_gemm_small<1>, cudaFuncAttributeMaxDynamicSharedMemorySize, SMEM_A);
        cudaFuncSetAttribute(k_gemm_gate<0>, cudaFuncAttributeMaxDynamicSharedMemorySize, SMEM_B);
        cudaFuncSetAttribute(k_gemm_gate<1>, cudaFuncAttributeMaxDynamicSharedMemorySize, SMEM_B);
    }

    __half *w1t, *w2t, *wgt, *q, *avg, *h, *f;
    cudaGetSymbolAddress((void**)&w1t, g_W1t);
    cudaGetSymbolAddress((void**)&w2t, g_W2t);
    cudaGetSymbolAddress((void**)&wgt, g_Wgt);
    cudaGetSymbolAddress((void**)&q,   g_q);
    cudaGetSymbolAddress((void**)&avg, g_avg);
    cudaGetSymbolAddress((void**)&h,   g_h);
    cudaGetSymbolAddress((void**)&f,   g_f);

    // fork
    cudaEventRecord(evRoot, 0);
    cudaStreamWaitEvent(s1, evRoot, 0);
    cudaStreamWaitEvent(s2, evRoot, 0);

    // branch s1: causal cumulative mean -> g_avg
    k_partial_sums<<<dim3(B_, NCH), D_, 0, s1>>>(iV);
    k_exclusive_prefix<<<B_, D_, 0, s1>>>();
    k_cumavg<<<dim3(B_, NCH), D_, 0, s1>>>(iV);
    cudaEventRecord(evScan, s1);

    // branch s2: converts for GEMM2/3, then the q-half gate GEMM (overlaps G1/G2)
    k_convert_W<<<dim3(D_ / 64, D_ / 64), 256, 0, s2>>>(W2, w2t, D_, D_);
    cudaEventRecord(evW2, s2);
    k_convert_W<<<dim3(2 * D_ / 64, 2 * D_ / 64), 256, 0, s2>>>(Wg, wgt, 2 * D_, 2 * D_);
    k_convert_iQ<<<(M_ * D_ / 32) / 256, 256, 0, s2>>>(iQ);
    k_gemm_gate<0><<<dim3(2 * D_ / BN, M_ / BM), 512, SMEM_B, s2>>>(q, nullptr, wgt, bg, out);
    cudaEventRecord(evGp, s2);

    // main stream: W1 convert, then GEMM chain with event joins
    k_convert_W<<<dim3(D_ / 64, D_ / 64), 256>>>(W1, w1t, D_, D_);
    cudaStreamWaitEvent(0, evScan, 0);
    k_gemm_small<0><<<dim3(D_ / 128, M_ / 128), 256, SMEM_A>>>(avg, w1t, b1);
    cudaStreamWaitEvent(0, evW2, 0);
    k_gemm_small<1><<<dim3(D_ / 128, M_ / 128), 256, SMEM_A>>>(h, w2t, b2);
    cudaStreamWaitEvent(0, evGp, 0);
    k_gemm_gate<1><<<dim3(2 * D_ / BN, M_ / BM), 512, SMEM_B>>>(f, q, wgt, bg, out);
}

// round 16
// speedup vs baseline: 1.1380x; 1.1380x over previous
#include <cuda_runtime.h>
#include <cuda_fp16.h>

#define B_   4
#define S_   2048
#define D_   1024
#define M_   (B_ * S_)          // 8192
#define NCH  64
#define CH   (S_ / NCH)         // 32
#define MCH  (M_ / 2)           // 4096 rows per chain

// ---------------- scratch ----------------------------------------------------
__device__ __align__(256) __half g_q  [(size_t)M_ * D_];
__device__ __align__(256) __half g_avg[(size_t)M_ * D_];
__device__ __align__(256) __half g_h  [(size_t)M_ * D_];
__device__ __align__(256) __half g_f  [(size_t)M_ * D_];
__device__ __align__(256) __half g_W1t[(size_t)D_ * D_];        // [N, K]
__device__ __align__(256) __half g_W2t[(size_t)D_ * D_];
__device__ __align__(256) __half g_Wgt[(size_t)2 * D_ * 2 * D_];
__device__ float g_part[B_ * NCH * D_];

// ---------------- helpers ----------------------------------------------------
__device__ __forceinline__ unsigned smem_u32(const void* p) {
    unsigned r;
    asm("{ .reg .u64 t; cvta.to.shared.u64 t, %1; cvt.u32.u64 %0, t; }" : "=r"(r) : "l"(p));
    return r;
}
__device__ __forceinline__ unsigned pk_f16(float a, float b) {
    return (unsigned)__half_as_ushort(__float2half_rn(a)) |
           ((unsigned)__half_as_ushort(__float2half_rn(b)) << 16);
}
__device__ __forceinline__ void ldsm4(unsigned& r0, unsigned& r1, unsigned& r2, unsigned& r3,
                                      unsigned addr) {
    asm volatile("ldmatrix.sync.aligned.m8n8.x4.shared.b16 {%0,%1,%2,%3}, [%4];"
                 : "=r"(r0), "=r"(r1), "=r"(r2), "=r"(r3) : "r"(addr));
}
__device__ __forceinline__ void mma_f16(float* c, unsigned a0, unsigned a1, unsigned a2,
                                        unsigned a3, unsigned b0, unsigned b1) {
    asm volatile(
        "mma.sync.aligned.m16n8k16.row.col.f32.f16.f16.f32 "
        "{%0,%1,%2,%3}, {%4,%5,%6,%7}, {%8,%9}, {%0,%1,%2,%3};"
        : "+f"(c[0]), "+f"(c[1]), "+f"(c[2]), "+f"(c[3])
        : "r"(a0), "r"(a1), "r"(a2), "r"(a3), "r"(b0), "r"(b1));
}

// ---------------- scan: causal cumulative mean -------------------------------
__global__ void k_partial_sums(const float* __restrict__ iV) {
    int b = blockIdx.x, ch = blockIdx.y, d = threadIdx.x;
    const float* p = iV + ((size_t)b * S_ + (size_t)ch * CH) * D_ + d;
    float s = 0.f;
#pragma unroll 8
    for (int t = 0; t < CH; t++) s += p[(size_t)t * D_];
    g_part[(b * NCH + ch) * D_ + d] = s;
}

__global__ void k_exclusive_prefix() {
    int b = blockIdx.x, d = threadIdx.x;
    float run = 0.f;
#pragma unroll
    for (int ch = 0; ch < NCH; ch++) {
        int idx = (b * NCH + ch) * D_ + d;
        float v = g_part[idx];
        g_part[idx] = run;
        run += v;
    }
}

__global__ void k_cumavg(const float* __restrict__ iV) {
    int b = blockIdx.x, ch = blockIdx.y, d = threadIdx.x;
    float run = g_part[(b * NCH + ch) * D_ + d];
    const float* p = iV + ((size_t)b * S_ + (size_t)ch * CH) * D_ + d;
    size_t mrow = (size_t)b * S_ + (size_t)ch * CH;
#pragma unroll 4
    for (int t = 0; t < CH; t++) {
        run += p[(size_t)t * D_];
        int s = ch * CH + t;
        float x = run * (1.0f / (float)(s + 1));
        g_avg[(mrow + t) * D_ + d] = __float2half_rn(x);
    }
}

// ---------------- conversions ------------------------------------------------
__global__ __launch_bounds__(256) void k_convert_iQ(const float* __restrict__ iQ) {
    size_t t = (size_t)blockIdx.x * blockDim.x + threadIdx.x;   // M_*D_/32 threads
    size_t m  = t / (D_ / 32);
    int    dq = (int)(t % (D_ / 32)) * 32;
    const float4* src = (const float4*)(iQ + m * D_ + dq);
    unsigned w[16];
#pragma unroll
    for (int i = 0; i < 8; i++) {
        float4 x = src[i];
        w[2 * i]     = pk_f16(x.x, x.y);
        w[2 * i + 1] = pk_f16(x.z, x.w);
    }
    uint4* dst = (uint4*)(g_q + m * D_ + dq);
#pragma unroll
    for (int i = 0; i < 4; i++)
        dst[i] = make_uint4(w[4 * i], w[4 * i + 1], w[4 * i + 2], w[4 * i + 3]);
}

// W [K,N] fp32 -> Wt [N, K] fp16, via smem transpose
__global__ __launch_bounds__(256) void k_convert_W(const float* __restrict__ W,
                                                   __half* __restrict__ Wt,
                                                   int K, int N) {
    __shared__ float t[64][65];
    const int tid = threadIdx.x;
    const int n0 = blockIdx.x * 64, k0 = blockIdx.y * 64;
    {
        const int r = tid >> 4;
        const int c4 = tid & 15;
#pragma unroll
        for (int i = 0; i < 4; i++) {
            int k = r + 16 * i;
            float4 v = *(const float4*)(W + (size_t)(k0 + k) * N + n0 + 4 * c4);
            t[k][4 * c4 + 0] = v.x;
            t[k][4 * c4 + 1] = v.y;
            t[k][4 * c4 + 2] = v.z;
            t[k][4 * c4 + 3] = v.w;
        }
    }
    __syncthreads();
    const int n = tid >> 2;
    const int kq = tid & 3;              // 16 orig-k each
    unsigned w[8];
#pragma unroll
    for (int j = 0; j < 8; j++)
        w[j] = pk_f16(t[16 * kq + 2 * j][n], t[16 * kq + 2 * j + 1][n]);
    uint4* dst = (uint4*)(Wt + (size_t)(n0 + n) * K + k0 + 16 * kq);
    dst[0] = make_uint4(w[0], w[1], w[2], w[3]);
    dst[1] = make_uint4(w[4], w[5], w[6], w[7]);
}

// ================= GEMM A: 128x128 tile, 256 threads, occ 2 ===================
#define BK 64
#define STAGES 3
#define STG_A (2 * 128 * 128)                // 32 KB per stage
#define SMEM_A (STAGES * STG_A)              // 96 KB

template <int SEL>
__global__ __launch_bounds__(256, 2)
void k_gemm_small(const __half* __restrict__ A0,
                  const __half* __restrict__ Bw,
                  const float* __restrict__ bias,
                  int m_base)
{
    extern __shared__ __align__(1024) char dsmem[];
    const unsigned sbase = smem_u32(dsmem);

    const int tid = threadIdx.x;
    const int warp = tid >> 5, lid = tid & 31;
    const int wm = warp >> 2;            // 0..1 -> 64 rows
    const int wn = warp & 3;             // 0..3 -> 32 cols
    const int m0 = m_base + blockIdx.y * 128;
    const int n0 = blockIdx.x * 128;
    const int NB = D_ / BK;              // 16

    const int lrow = tid >> 1;           // 0..127
    const int lcb  = (tid & 1) * 4;
    const int lswz = lrow & 7;

    float acc[4][4][4];
#pragma unroll
    for (int i = 0; i < 4; i++)
#pragma unroll
        for (int j = 0; j < 4; j++)
#pragma unroll
            for (int k = 0; k < 4; k++) acc[i][j][k] = 0.f;

    auto load_blk = [&](int kb, int stage) {
        unsigned sA = sbase + stage * STG_A;
        unsigned sB = sA + 128 * 128;
        unsigned long long ag =
            (unsigned long long)(A0 + (size_t)(m0 + lrow) * D_ + (size_t)kb * BK);
        unsigned asm_ = sA + lrow * 128;
#pragma unroll
        for (int i = 0; i < 4; i++) {
            int c = lcb + i;
            asm volatile("cp.async.cg.shared.global [%0], [%1], 16;"
                         :: "r"(asm_ + (unsigned)((c ^ lswz) << 4)), "l"(ag + c * 16) : "memory");
        }
        unsigned long long bg2 =
            (unsigned long long)(Bw + (size_t)(n0 + lrow) * D_ + (size_t)kb * BK);
        unsigned bsm = sB + lrow * 128;
#pragma unroll
        for (int i = 0; i < 4; i++) {
            int c = lcb + i;
            asm volatile("cp.async.cg.shared.global [%0], [%1], 16;"
                         :: "r"(bsm + (unsigned)((c ^ lswz) << 4)), "l"(bg2 + c * 16) : "memory");
        }
        asm volatile("cp.async.commit_group;" ::: "memory");
    };

    int arow[4], brow[2];
#pragma unroll
    for (int mt = 0; mt < 4; mt++)
        arow[mt] = wm * 64 + mt * 16 + (lid & 7) + ((lid >> 3) & 1) * 8;
    const int ahi = lid >> 4;
#pragma unroll
    for (int p = 0; p < 2; p++)
        brow[p] = wn * 32 + p * 16 + (lid & 7) + (lid >> 4) * 8;
    const int bhi = (lid >> 3) & 1;

#pragma unroll
    for (int s = 0; s < STAGES - 1; s++) load_blk(s, s);

    for (int kb = 0; kb < NB; kb++) {
        asm volatile("cp.async.wait_group %0;" :: "n"(STAGES - 2) : "memory");
        __syncthreads();
        if (kb + STAGES - 1 < NB) load_blk(kb + STAGES - 1, (kb + STAGES - 1) % STAGES);

        unsigned sA = sbase + (kb % STAGES) * STG_A;
        unsigned sB = sA + 128 * 128;
#pragma unroll
        for (int ks = 0; ks < 4; ks++) {
            unsigned a[4][4], b[2][4];
#pragma unroll
            for (int mt = 0; mt < 4; mt++)
                ldsm4(a[mt][0], a[mt][1], a[mt][2], a[mt][3],
                      sA + arow[mt] * 128 + (unsigned)(((2 * ks + ahi) ^ (arow[mt] & 7)) << 4));
#pragma unroll
            for (int p = 0; p < 2; p++)
                ldsm4(b[p][0], b[p][1], b[p][2], b[p][3],
                      sB + brow[p] * 128 + (unsigned)(((2 * ks + bhi) ^ (brow[p] & 7)) << 4));
#pragma unroll
            for (int mt = 0; mt < 4; mt++)
#pragma unroll
                for (int nt = 0; nt < 4; nt++)
                    mma_f16(acc[mt][nt], a[mt][0], a[mt][1], a[mt][2], a[mt][3],
                            b[nt >> 1][(nt & 1) * 2], b[nt >> 1][(nt & 1) * 2 + 1]);
        }
    }

    const int gid = lid >> 2, tig = lid & 3;
#pragma unroll
    for (int mt = 0; mt < 4; mt++) {
#pragma unroll
        for (int r2 = 0; r2 < 2; r2++) {
            const int m = m0 + wm * 64 + mt * 16 + gid + r2 * 8;
#pragma unroll
            for (int nt = 0; nt < 4; nt++) {
                const int n = n0 + wn * 32 + nt * 8 + 2 * tig;
                float2 bb = *(const float2*)(bias + n);
                float v0 = acc[mt][nt][r2 * 2 + 0] + bb.x;
                float v1 = acc[mt][nt][r2 * 2 + 1] + bb.y;
                if (SEL == 0) {
                    v0 = fmaxf(v0, 0.f); v1 = fmaxf(v1, 0.f);
                    *(unsigned*)(g_h + (size_t)m * D_ + n) = pk_f16(v0, v1);
                } else {
                    *(unsigned*)(g_f + (size_t)m * D_ + n) = pk_f16(v0, v1);
                }
            }
        }
    }
}

// ================= GEMM B: gate GEMM + combine (128x256, 512 thr) =============
#define BM 128
#define BN 256
#define A_BYTES (BM * 128)                  // 16 KB
#define B_BYTES (BN * 128)                  // 32 KB
#define STG_B (A_BYTES + B_BYTES)           // 48 KB
#define SMEM_B (STAGES * STG_B)             // 144 KB

__global__ __launch_bounds__(512, 1)
void k_gemm_gate(const __half* __restrict__ A0,     // g_q
                 const __half* __restrict__ A1,     // g_f
                 const __half* __restrict__ Bw,     // g_Wgt
                 const float* __restrict__ bias,
                 float* __restrict__ out,
                 int m_base)
{
    extern __shared__ __align__(1024) char dsmem[];
    const unsigned sbase = smem_u32(dsmem);
    const int K = 2 * D_;

    const int tid = threadIdx.x;
    const int warp = tid >> 5, lid = tid & 31;
    const int wm = warp >> 3;            // 0..1
    const int wn = warp & 7;             // 0..7
    const int m0 = m_base + blockIdx.y * BM;
    const int cg0 = blockIdx.x * 128;    // gate col-pair base
    const int NB = K / BK;               // 32

    const int ar  = tid >> 2;            // 0..127
    const int ac0 = (tid & 3) * 2;
    const int br  = tid >> 1;            // 0..255
    const int bc0 = (tid & 1) * 4;

    float acc[4][4][4];
#pragma unroll
    for (int i = 0; i < 4; i++)
#pragma unroll
        for (int j = 0; j < 4; j++)
#pragma unroll
            for (int k = 0; k < 4; k++) acc[i][j][k] = 0.f;

    auto load_blk = [&](int kb, int stage) {
        unsigned sA = sbase + stage * STG_B;
        unsigned sB = sA + A_BYTES;
        const __half* Arow;
        if (kb >= 16) Arow = A1 + (size_t)(m0 + ar) * D_ + (size_t)(kb - 16) * BK;
        else          Arow = A0 + (size_t)(m0 + ar) * D_ + (size_t)kb * BK;
        unsigned long long ag = (unsigned long long)Arow;
        unsigned asm_ = sA + ar * 128;
        const int aswz = ar & 7;
#pragma unroll
        for (int i = 0; i < 2; i++) {
            int c = ac0 + i;
            asm volatile("cp.async.cg.shared.global [%0], [%1], 16;"
                         :: "r"(asm_ + (unsigned)((c ^ aswz) << 4)), "l"(ag + c * 16) : "memory");
        }
        int gn = (br < 128) ? (cg0 + br) : (1024 + cg0 + br - 128);
        unsigned long long bg2 = (unsigned long long)(Bw + (size_t)gn * K + (size_t)kb * BK);
        unsigned bsm = sB + br * 128;
        const int bswz = br & 7;
#pragma unroll
        for (int i = 0; i < 4; i++) {
            int c = bc0 + i;
            asm volatile("cp.async.cg.shared.global [%0], [%1], 16;"
                         :: "r"(bsm + (unsigned)((c ^ bswz) << 4)), "l"(bg2 + c * 16) : "memory");
        }
        asm volatile("cp.async.commit_group;" ::: "memory");
    };

    int arow[4], brow[2];
#pragma unroll
    for (int mt = 0; mt < 4; mt++)
        arow[mt] = wm * 64 + mt * 16 + (lid & 7) + ((lid >> 3) & 1) * 8;
    const int ahi = lid >> 4;
#pragma unroll
    for (int p = 0; p < 2; p++)
        brow[p] = wn * 32 + p * 16 + (lid & 7) + (lid >> 4) * 8;
    const int bhi = (lid >> 3) & 1;

#pragma unroll
    for (int s = 0; s < STAGES - 1; s++) load_blk(s, s);

    for (int kb = 0; kb < NB; kb++) {
        asm volatile("cp.async.wait_group %0;" :: "n"(STAGES - 2) : "memory");
        __syncthreads();
        if (kb + STAGES - 1 < NB) load_blk(kb + STAGES - 1, (kb + STAGES - 1) % STAGES);

        unsigned sA = sbase + (kb % STAGES) * STG_B;
        unsigned sB = sA + A_BYTES;
#pragma unroll
        for (int ks = 0; ks < 4; ks++) {
            unsigned a[4][4], b[2][4];
#pragma unroll
            for (int mt = 0; mt < 4; mt++)
                ldsm4(a[mt][0], a[mt][1], a[mt][2], a[mt][3],
                      sA + arow[mt] * 128 + (unsigned)(((2 * ks + ahi) ^ (arow[mt] & 7)) << 4));
#pragma unroll
            for (int p = 0; p < 2; p++)
                ldsm4(b[p][0], b[p][1], b[p][2], b[p][3],
                      sB + brow[p] * 128 + (unsigned)(((2 * ks + bhi) ^ (brow[p] & 7)) << 4));
#pragma unroll
            for (int mt = 0; mt < 4; mt++)
#pragma unroll
                for (int nt = 0; nt < 4; nt++)
                    mma_f16(acc[mt][nt], a[mt][0], a[mt][1], a[mt][2], a[mt][3],
                            b[nt >> 1][(nt & 1) * 2], b[nt >> 1][(nt & 1) * 2 + 1]);
        }
    }

    // gate exchange + fused combine
    const int gid = lid >> 2, tig = lid & 3;
    __syncthreads();
    float* gsm = (float*)dsmem;        // [128][260]
#pragma unroll
    for (int mt = 0; mt < 4; mt++) {
#pragma unroll
        for (int r2 = 0; r2 < 2; r2++) {
            const int ml = wm * 64 + mt * 16 + gid + r2 * 8;
#pragma unroll
            for (int nt = 0; nt < 4; nt++) {
                const int nl = wn * 32 + nt * 8 + 2 * tig;
                const int gcol = (nl < 128) ? (cg0 + nl) : (1024 + cg0 + nl - 128);
                float2 bb = *(const float2*)(bias + gcol);
                float v0 = acc[mt][nt][r2 * 2 + 0] + bb.x;
                float v1 = acc[mt][nt][r2 * 2 + 1] + bb.y;
                v0 = 1.0f / (1.0f + __expf(-v0));
                v1 = 1.0f / (1.0f + __expf(-v1));
                gsm[ml * 260 + nl]     = v0;
                gsm[ml * 260 + nl + 1] = v1;
            }
        }
    }
    __syncthreads();
    const int c4 = tid & 31;
    const int r0 = tid >> 5;
#pragma unroll
    for (int i = 0; i < 8; i++) {
        const int r = r0 + 16 * i;
        const int col = 4 * c4;
        const size_t gidx = (size_t)(m0 + r) * D_ + cg0 + col;
        uint2 qw = *(const uint2*)(A0 + gidx);
        uint2 fw = *(const uint2*)(A1 + gidx);
        float2 q01 = __half22float2(*(__half2*)&qw.x);
        float2 q23 = __half22float2(*(__half2*)&qw.y);
        float2 f01 = __half22float2(*(__half2*)&fw.x);
        float2 f23 = __half22float2(*(__half2*)&fw.y);
        float4 gi = *(const float4*)&gsm[r * 260 + col];
        float4 gf = *(const float4*)&gsm[r * 260 + 128 + col];
        float4 o;
        o.x = gi.x * q01.x + gf.x * f01.x;
        o.y = gi.y * q01.y + gf.y * f01.y;
        o.z = gi.z * q23.x + gf.z * f23.x;
        o.w = gi.w * q23.y + gf.w * f23.y;
        *(float4*)(out + gidx) = o;
    }
}

// ---------------- launch ------------------------------------------------------
extern "C" void kernel_launch(void* const* d_in, const int* in_sizes, int n_in,
                              void* d_out, int out_size) {
    const float* iQ = (const float*)d_in[0];
    const float* iV = (const float*)d_in[1];
    const float* W1 = (const float*)d_in[2];
    const float* b1 = (const float*)d_in[3];
    const float* W2 = (const float*)d_in[4];
    const float* b2 = (const float*)d_in[5];
    const float* Wg = (const float*)d_in[6];
    const float* bg = (const float*)d_in[7];
    float* out = (float*)d_out;

    // one-time host-side resources — EXACTLY 2 streams (R13-proven safe)
    static cudaStream_t s1 = nullptr, s2 = nullptr;
    static cudaEvent_t evRoot, evScan, evW1, evW2, evPrep, evDone1;
    if (s1 == nullptr) {
        cudaStreamCreateWithFlags(&s1, cudaStreamNonBlocking);
        cudaStreamCreateWithFlags(&s2, cudaStreamNonBlocking);
        cudaEventCreateWithFlags(&evRoot,  cudaEventDisableTiming);
        cudaEventCreateWithFlags(&evScan,  cudaEventDisableTiming);
        cudaEventCreateWithFlags(&evW1,    cudaEventDisableTiming);
        cudaEventCreateWithFlags(&evW2,    cudaEventDisableTiming);
        cudaEventCreateWithFlags(&evPrep,  cudaEventDisableTiming);
        cudaEventCreateWithFlags(&evDone1, cudaEventDisableTiming);
        cudaFuncSetAttribute(k_gemm_small<0>, cudaFuncAttributeMaxDynamicSharedMemorySize, SMEM_A);
        cudaFuncSetAttribute(k_gemm_small<1>, cudaFuncAttributeMaxDynamicSharedMemorySize, SMEM_A);
        cudaFuncSetAttribute(k_gemm_gate, cudaFuncAttributeMaxDynamicSharedMemorySize, SMEM_B);
    }

    __half *w1t, *w2t, *wgt, *q, *avg, *h, *f;
    cudaGetSymbolAddress((void**)&w1t, g_W1t);
    cudaGetSymbolAddress((void**)&w2t, g_W2t);
    cudaGetSymbolAddress((void**)&wgt, g_Wgt);
    cudaGetSymbolAddress((void**)&q,   g_q);
    cudaGetSymbolAddress((void**)&avg, g_avg);
    cudaGetSymbolAddress((void**)&h,   g_h);
    cudaGetSymbolAddress((void**)&f,   g_f);

    // fork
    cudaEventRecord(evRoot, 0);
    cudaStreamWaitEvent(s1, evRoot, 0);
    cudaStreamWaitEvent(s2, evRoot, 0);

    // s1: causal cumulative mean -> g_avg
    k_partial_sums<<<dim3(B_, NCH), D_, 0, s1>>>(iV);
    k_exclusive_prefix<<<B_, D_, 0, s1>>>();
    k_cumavg<<<dim3(B_, NCH), D_, 0, s1>>>(iV);
    cudaEventRecord(evScan, s1);

    // s2: converts for GEMM2 / GEMM3
    k_convert_W<<<dim3(D_ / 64, D_ / 64), 256, 0, s2>>>(W2, w2t, D_, D_);
    cudaEventRecord(evW2, s2);
    k_convert_W<<<dim3(2 * D_ / 64, 2 * D_ / 64), 256, 0, s2>>>(Wg, wgt, 2 * D_, 2 * D_);
    k_convert_iQ<<<(M_ * D_ / 32) / 256, 256, 0, s2>>>(iQ);
    cudaEventRecord(evPrep, s2);

    // main: W1 convert
    k_convert_W<<<dim3(D_ / 64, D_ / 64), 256>>>(W1, w1t, D_, D_);
    cudaEventRecord(evW1, 0);

    // chain 0 (rows 0..4095) on the default stream
    cudaStreamWaitEvent(0, evScan, 0);
    k_gemm_small<0><<<dim3(D_ / 128, MCH / 128), 256, SMEM_A>>>(avg, w1t, b1, 0);
    cudaStreamWaitEvent(0, evW2, 0);
    k_gemm_small<1><<<dim3(D_ / 128, MCH / 128), 256, SMEM_A>>>(h, w2t, b2, 0);
    cudaStreamWaitEvent(0, evPrep, 0);
    k_gemm_gate<<<dim3(2 * D_ / BN, MCH / BM), 512, SMEM_B>>>(q, f, wgt, bg, out, 0);

    // chain 1 (rows 4096..8191) on s1 (scan already done there)
    cudaStreamWaitEvent(s1, evW1, 0);
    k_gemm_small<0><<<dim3(D_ / 128, MCH / 128), 256, SMEM_A, s1>>>(avg, w1t, b1, MCH);
    cudaStreamWaitEvent(s1, evW2, 0);
    k_gemm_small<1><<<dim3(D_ / 128, MCH / 128), 256, SMEM_A, s1>>>(h, w2t, b2, MCH);
    cudaStreamWaitEvent(s1, evPrep, 0);
    k_gemm_gate<<<dim3(2 * D_ / BN, MCH / BM), 512, SMEM_B, s1>>>(q, f, wgt, bg, out, MCH);
    cudaEventRecord(evDone1, s1);

    // join
    cudaStreamWaitEvent(0, evDone1, 0);
}